// round 6
// baseline (speedup 1.0000x reference)
#include <cuda_runtime.h>
#include <cuda_fp16.h>
#include <cstdint>

// ---------------------------------------------------------------------------
// y[8192,16384] = x[8192,4096] @ dequant(W[4096,16384]) * scale + bias
// NOTE: harness delivers the "int8" weight as int32 (supported dtypes are
// f32/i32/bf16 only). Reading it as int8 was the source of rel_err=sqrt(1.25).
// HMMA m16n8k16 pipelined GEMM, K-major A and B smem, non-trans ldmatrix.
// ---------------------------------------------------------------------------
static constexpr int M_ROWS = 8192;
static constexpr int K_DIM  = 4096;
static constexpr int N_DIM  = 16384;

static constexpr int BM = 128;
static constexpr int BN = 256;
static constexpr int BK = 32;
static constexpr int STAGES = 4;
static constexpr int NITER  = K_DIM / BK;     // 128

static constexpr int A_LD = BK + 8;           // 40 halves = 80 B
static constexpr int B_LD = BK + 8;
static constexpr int A_ST = BM * A_LD;        // 5120 halves
static constexpr int B_ST = BN * B_LD;        // 10240 halves
static constexpr int STG  = A_ST + B_ST;      // 15360 halves = 30720 B
static constexpr int SMEM_BYTES = STAGES * STG * 2;   // 122880 B

__device__ __half g_xh[(size_t)M_ROWS * K_DIM];   //  64 MiB  [M][K]
__device__ __half g_wh[(size_t)N_DIM * K_DIM];    // 128 MiB  [N][K]

// ---------------------------------------------------------------------------
__device__ __forceinline__ uint32_t smem_u32(const void* p) {
    uint32_t a;
    asm("{ .reg .u64 t; cvta.to.shared.u64 t, %1; cvt.u32.u64 %0, t; }" : "=r"(a) : "l"(p));
    return a;
}

__device__ __forceinline__ void cp16(uint32_t dst, const void* src) {
    asm volatile("cp.async.cg.shared.global [%0], [%1], 16;" :: "r"(dst), "l"(src));
}

#define CP_COMMIT() asm volatile("cp.async.commit_group;" ::: "memory")

__device__ __forceinline__ void ldsm4(uint32_t* r, uint32_t addr) {
    asm volatile("ldmatrix.sync.aligned.m8n8.x4.shared.b16 {%0,%1,%2,%3}, [%4];"
                 : "=r"(r[0]), "=r"(r[1]), "=r"(r[2]), "=r"(r[3]) : "r"(addr));
}

__device__ __forceinline__ void mma16816(float* d, const uint32_t* a, uint32_t b0, uint32_t b1) {
    asm volatile(
        "mma.sync.aligned.m16n8k16.row.col.f32.f16.f16.f32 "
        "{%0,%1,%2,%3}, {%4,%5,%6,%7}, {%8,%9}, {%0,%1,%2,%3};"
        : "+f"(d[0]), "+f"(d[1]), "+f"(d[2]), "+f"(d[3])
        : "r"(a[0]), "r"(a[1]), "r"(a[2]), "r"(a[3]), "r"(b0), "r"(b1));
}

// ---------------------------------------------------------------------------
// Prep kernels
// ---------------------------------------------------------------------------
__global__ void cvt_x_kernel(const float4* __restrict__ x, __half2* __restrict__ out, int n4) {
    int i = blockIdx.x * blockDim.x + threadIdx.x;
    if (i < n4) {
        float4 v = x[i];
        out[2 * i]     = __floats2half2_rn(v.x, v.y);
        out[2 * i + 1] = __floats2half2_rn(v.z, v.w);
    }
}

// W[k][n] int32 row-major -> Wh[n][k] fp16 (exact for |w|<=128), 32x32 transpose
__global__ void cvt_w_kernel(const int* __restrict__ w, __half* __restrict__ out) {
    __shared__ int t[32][33];
    int n0 = blockIdx.x * 32, k0 = blockIdx.y * 32;
    int tx = threadIdx.x, ty = threadIdx.y;
    #pragma unroll
    for (int i = ty; i < 32; i += 8)
        t[i][tx] = w[(size_t)(k0 + i) * N_DIM + n0 + tx];   // t[k_local][n_local]
    __syncthreads();
    #pragma unroll
    for (int i = ty; i < 32; i += 8)
        out[(size_t)(n0 + i) * K_DIM + k0 + tx] = __int2half_rn(t[tx][i]);
}

// ---------------------------------------------------------------------------
// Main GEMM
// ---------------------------------------------------------------------------
__global__ void __launch_bounds__(256, 1) qgemm_kernel(
    const float* __restrict__ scale,
    const float* __restrict__ bias,
    float* __restrict__ out)
{
    extern __shared__ __align__(16) char smem_raw[];
    const uint32_t sb = smem_u32(smem_raw);
    const int tid = threadIdx.x;
    const int wid = tid >> 5;
    const int lid = tid & 31;

    const int bid = blockIdx.x;
    const int group  = bid >> 9;
    const int within = bid & 511;
    const int nt = (group << 3) | (within & 7);
    const int mt = within >> 3;
    const int m0 = mt * BM;
    const int n0 = nt * BN;

    const __half* __restrict__ xh = g_xh;
    const __half* __restrict__ wh = g_wh;

    auto issue_stage = [&](int it) {
        const int k0 = it * BK;
        const uint32_t base = (uint32_t)(it & (STAGES - 1)) * (STG * 2) + sb;
        #pragma unroll
        for (int j = 0; j < 2; ++j) {
            int ci = tid + 256 * j;
            int row = ci >> 2, cc = ci & 3;
            cp16(base + (uint32_t)(row * A_LD + cc * 8) * 2,
                 xh + (size_t)(m0 + row) * K_DIM + k0 + cc * 8);
        }
        #pragma unroll
        for (int j = 0; j < 4; ++j) {
            int ci = tid + 256 * j;
            int row = ci >> 2, cc = ci & 3;
            cp16(base + (uint32_t)(A_ST + row * B_LD + cc * 8) * 2,
                 wh + (size_t)(n0 + row) * K_DIM + k0 + cc * 8);
        }
        CP_COMMIT();
    };

    const int wmb = (wid & 1) * 64;
    const int wnb = (wid >> 1) * 64;

    float acc[4][8][4];
    #pragma unroll
    for (int i = 0; i < 4; ++i)
        #pragma unroll
        for (int j = 0; j < 8; ++j)
            #pragma unroll
            for (int k = 0; k < 4; ++k) acc[i][j][k] = 0.0f;

    #pragma unroll
    for (int s = 0; s < STAGES - 1; ++s) issue_stage(s);

    const int a_row_lane = lid & 15;
    const int a_col_lane = (lid >> 4) * 8;
    const int b_row_lane = (lid & 7) | ((lid >> 4) << 3);
    const int b_col_lane = ((lid >> 3) & 1) * 8;

    #pragma unroll 1
    for (int it = 0; it < NITER; ++it) {
        asm volatile("cp.async.wait_group 2;" ::: "memory");
        __syncthreads();
        if (it + STAGES - 1 < NITER) issue_stage(it + STAGES - 1);
        else CP_COMMIT();

        const uint32_t base = (uint32_t)(it & (STAGES - 1)) * (STG * 2) + sb;
        #pragma unroll
        for (int ks = 0; ks < 2; ++ks) {
            uint32_t a[4][4], b[4][4];
            #pragma unroll
            for (int mf = 0; mf < 4; ++mf) {
                int row = wmb + mf * 16 + a_row_lane;
                int col = ks * 16 + a_col_lane;
                ldsm4(a[mf], base + (uint32_t)(row * A_LD + col) * 2);
            }
            #pragma unroll
            for (int nf2 = 0; nf2 < 4; ++nf2) {
                int row = wnb + nf2 * 16 + b_row_lane;
                int col = ks * 16 + b_col_lane;
                ldsm4(b[nf2], base + (uint32_t)(A_ST + row * B_LD + col) * 2);
            }
            #pragma unroll
            for (int mf = 0; mf < 4; ++mf) {
                #pragma unroll
                for (int nf2 = 0; nf2 < 4; ++nf2) {
                    mma16816(acc[mf][nf2 * 2],     a[mf], b[nf2][0], b[nf2][1]);
                    mma16816(acc[mf][nf2 * 2 + 1], a[mf], b[nf2][2], b[nf2][3]);
                }
            }
        }
    }

    // ---- Epilogue: fused scale/bias, float2 stores ----
    const int ncol0 = n0 + wnb;
    float2 sc[8], bi[8];
    #pragma unroll
    for (int nf = 0; nf < 8; ++nf) {
        int c = nf * 8 + (lid & 3) * 2;
        sc[nf] = *reinterpret_cast<const float2*>(scale + ncol0 + c);
        bi[nf] = *reinterpret_cast<const float2*>(bias + ncol0 + c);
    }
    #pragma unroll
    for (int mf = 0; mf < 4; ++mf) {
        int r0 = m0 + wmb + mf * 16 + (lid >> 2);
        float* out0 = out + (size_t)r0 * N_DIM + ncol0;
        float* out1 = out0 + (size_t)8 * N_DIM;
        #pragma unroll
        for (int nf = 0; nf < 8; ++nf) {
            int c = nf * 8 + (lid & 3) * 2;
            float2 v0 = make_float2(fmaf(acc[mf][nf][0], sc[nf].x, bi[nf].x),
                                    fmaf(acc[mf][nf][1], sc[nf].y, bi[nf].y));
            float2 v1 = make_float2(fmaf(acc[mf][nf][2], sc[nf].x, bi[nf].x),
                                    fmaf(acc[mf][nf][3], sc[nf].y, bi[nf].y));
            *reinterpret_cast<float2*>(out0 + c) = v0;
            *reinterpret_cast<float2*>(out1 + c) = v1;
        }
    }
}

// ---------------------------------------------------------------------------
// Host launch — inputs identified by element count.
//   x: 33554432 f32 | weight: 67108864 (delivered as int32) | scale/bias: 16384 f32
// ---------------------------------------------------------------------------
extern "C" void kernel_launch(void* const* d_in, const int* in_sizes, int n_in,
                              void* d_out, int out_size) {
    int xi = 0, wi = 1, sm1 = -1, sm2 = -1;
    for (int i = 0; i < 4; ++i) {
        if (in_sizes[i] == M_ROWS * K_DIM)      xi = i;
        else if (in_sizes[i] == K_DIM * N_DIM)  wi = i;
        else if (sm1 < 0)                       sm1 = i;
        else                                    sm2 = i;
    }
    int si, bi2;
    if (xi < sm1) { si = sm1; bi2 = sm2; }   // dict order: x, w, scale, bias
    else          { bi2 = sm1; si = sm2; }   // alphabetical: bias, scale, w, x

    const float* x     = (const float*)d_in[xi];
    const int*   w     = (const int*)d_in[wi];     // int8 promoted to int32 by harness
    const float* scale = (const float*)d_in[si];
    const float* bias  = (const float*)d_in[bi2];
    float*       out   = (float*)d_out;

    void* xh = nullptr; cudaGetSymbolAddress(&xh, g_xh);
    void* wh = nullptr; cudaGetSymbolAddress(&wh, g_wh);

    int nx4 = M_ROWS * K_DIM / 4;
    cvt_x_kernel<<<nx4 / 256, 256>>>((const float4*)x, (__half2*)xh, nx4);
    cvt_w_kernel<<<dim3(N_DIM / 32, K_DIM / 32), dim3(32, 8)>>>(w, (__half*)wh);

    cudaFuncSetAttribute(qgemm_kernel, cudaFuncAttributeMaxDynamicSharedMemorySize,
                         SMEM_BYTES);
    int grid = (M_ROWS / BM) * (N_DIM / BN);   // 4096
    qgemm_kernel<<<grid, 256, SMEM_BYTES>>>(scale, bias, out);
}

// round 7
// speedup vs baseline: 1.1608x; 1.1608x over previous
#include <cuda_runtime.h>
#include <cuda_fp16.h>
#include <cstdint>

// ---------------------------------------------------------------------------
// y[8192,16384] = x[8192,4096] @ dequant(W[4096,16384]) * scale + bias
// Weight arrives as int32 (harness dtype set is f32/i32/bf16).
// HMMA m16n8k16 pipelined GEMM, K-major A/B smem, non-trans ldmatrix.
// R7: BK=64, 3 stages -> half the barriers, longer MMA runs per barrier.
// ---------------------------------------------------------------------------
static constexpr int M_ROWS = 8192;
static constexpr int K_DIM  = 4096;
static constexpr int N_DIM  = 16384;

static constexpr int BM = 128;
static constexpr int BN = 256;
static constexpr int BK = 64;
static constexpr int STAGES = 3;
static constexpr int NITER  = K_DIM / BK;     // 64

static constexpr int A_LD = BK + 8;           // 72 halves = 144 B (16B mult)
static constexpr int B_LD = BK + 8;
static constexpr int A_ST = BM * A_LD;        // 9216 halves
static constexpr int B_ST = BN * B_LD;        // 18432 halves
static constexpr int STG  = A_ST + B_ST;      // 27648 halves = 55296 B
static constexpr int SMEM_BYTES = STAGES * STG * 2;   // 165888 B

__device__ __half g_xh[(size_t)M_ROWS * K_DIM];   //  64 MiB  [M][K]
__device__ __half g_wh[(size_t)N_DIM * K_DIM];    // 128 MiB  [N][K]

// ---------------------------------------------------------------------------
__device__ __forceinline__ uint32_t smem_u32(const void* p) {
    uint32_t a;
    asm("{ .reg .u64 t; cvta.to.shared.u64 t, %1; cvt.u32.u64 %0, t; }" : "=r"(a) : "l"(p));
    return a;
}

__device__ __forceinline__ void cp16(uint32_t dst, const void* src) {
    asm volatile("cp.async.cg.shared.global [%0], [%1], 16;" :: "r"(dst), "l"(src));
}

#define CP_COMMIT() asm volatile("cp.async.commit_group;" ::: "memory")

__device__ __forceinline__ void ldsm4(uint32_t* r, uint32_t addr) {
    asm volatile("ldmatrix.sync.aligned.m8n8.x4.shared.b16 {%0,%1,%2,%3}, [%4];"
                 : "=r"(r[0]), "=r"(r[1]), "=r"(r[2]), "=r"(r[3]) : "r"(addr));
}

__device__ __forceinline__ void mma16816(float* d, const uint32_t* a, uint32_t b0, uint32_t b1) {
    asm volatile(
        "mma.sync.aligned.m16n8k16.row.col.f32.f16.f16.f32 "
        "{%0,%1,%2,%3}, {%4,%5,%6,%7}, {%8,%9}, {%0,%1,%2,%3};"
        : "+f"(d[0]), "+f"(d[1]), "+f"(d[2]), "+f"(d[3])
        : "r"(a[0]), "r"(a[1]), "r"(a[2]), "r"(a[3]), "r"(b0), "r"(b1));
}

// ---------------------------------------------------------------------------
// Prep kernels
// ---------------------------------------------------------------------------
__global__ void cvt_x_kernel(const float4* __restrict__ x, __half2* __restrict__ out, int n4) {
    int i = blockIdx.x * blockDim.x + threadIdx.x;
    if (i < n4) {
        float4 v = x[i];
        out[2 * i]     = __floats2half2_rn(v.x, v.y);
        out[2 * i + 1] = __floats2half2_rn(v.z, v.w);
    }
}

// W[k][n] int32 row-major -> Wh[n][k] fp16 (exact), 32x32 smem transpose
__global__ void cvt_w_kernel(const int* __restrict__ w, __half* __restrict__ out) {
    __shared__ int t[32][33];
    int n0 = blockIdx.x * 32, k0 = blockIdx.y * 32;
    int tx = threadIdx.x, ty = threadIdx.y;
    #pragma unroll
    for (int i = ty; i < 32; i += 8)
        t[i][tx] = w[(size_t)(k0 + i) * N_DIM + n0 + tx];
    __syncthreads();
    #pragma unroll
    for (int i = ty; i < 32; i += 8)
        out[(size_t)(n0 + i) * K_DIM + k0 + tx] = __int2half_rn(t[tx][i]);
}

// ---------------------------------------------------------------------------
// Main GEMM
// ---------------------------------------------------------------------------
__global__ void __launch_bounds__(256, 1) qgemm_kernel(
    const float* __restrict__ scale,
    const float* __restrict__ bias,
    float* __restrict__ out)
{
    extern __shared__ __align__(16) char smem_raw[];
    const uint32_t sb = smem_u32(smem_raw);
    const int tid = threadIdx.x;
    const int wid = tid >> 5;
    const int lid = tid & 31;

    const int bid = blockIdx.x;
    const int group  = bid >> 9;
    const int within = bid & 511;
    const int nt = (group << 3) | (within & 7);
    const int mt = within >> 3;
    const int m0 = mt * BM;
    const int n0 = nt * BN;

    const __half* __restrict__ xh = g_xh;
    const __half* __restrict__ wh = g_wh;

    auto issue_stage = [&](int it) {
        const int k0 = it * BK;
        const uint32_t base = sb + (uint32_t)(it % STAGES) * (STG * 2);
        // A: 128 rows x 8 chunks = 1024 -> 4/thread
        #pragma unroll
        for (int j = 0; j < 4; ++j) {
            int ci = tid + 256 * j;
            int row = ci >> 3, cc = ci & 7;
            cp16(base + (uint32_t)(row * A_LD + cc * 8) * 2,
                 xh + (size_t)(m0 + row) * K_DIM + k0 + cc * 8);
        }
        // B: 256 rows x 8 chunks = 2048 -> 8/thread
        #pragma unroll
        for (int j = 0; j < 8; ++j) {
            int ci = tid + 256 * j;
            int row = ci >> 3, cc = ci & 7;
            cp16(base + (uint32_t)(A_ST + row * B_LD + cc * 8) * 2,
                 wh + (size_t)(n0 + row) * K_DIM + k0 + cc * 8);
        }
        CP_COMMIT();
    };

    const int wmb = (wid & 1) * 64;
    const int wnb = (wid >> 1) * 64;

    float acc[4][8][4];
    #pragma unroll
    for (int i = 0; i < 4; ++i)
        #pragma unroll
        for (int j = 0; j < 8; ++j)
            #pragma unroll
            for (int k = 0; k < 4; ++k) acc[i][j][k] = 0.0f;

    issue_stage(0);
    issue_stage(1);

    const int a_row_lane = lid & 15;
    const int a_col_lane = (lid >> 4) * 8;
    const int b_row_lane = (lid & 7) | ((lid >> 4) << 3);
    const int b_col_lane = ((lid >> 3) & 1) * 8;

    #pragma unroll 1
    for (int it = 0; it < NITER; ++it) {
        asm volatile("cp.async.wait_group 1;" ::: "memory");
        __syncthreads();
        if (it + 2 < NITER) issue_stage(it + 2);
        else CP_COMMIT();   // keep 1 commit/iter so wait_group count stays valid

        const uint32_t base = sb + (uint32_t)(it % STAGES) * (STG * 2);
        #pragma unroll
        for (int ks = 0; ks < BK / 16; ++ks) {
            uint32_t a[4][4], b[4][4];
            #pragma unroll
            for (int mf = 0; mf < 4; ++mf) {
                int row = wmb + mf * 16 + a_row_lane;
                int col = ks * 16 + a_col_lane;
                ldsm4(a[mf], base + (uint32_t)(row * A_LD + col) * 2);
            }
            #pragma unroll
            for (int nf2 = 0; nf2 < 4; ++nf2) {
                int row = wnb + nf2 * 16 + b_row_lane;
                int col = ks * 16 + b_col_lane;
                ldsm4(b[nf2], base + (uint32_t)(A_ST + row * B_LD + col) * 2);
            }
            #pragma unroll
            for (int mf = 0; mf < 4; ++mf) {
                #pragma unroll
                for (int nf2 = 0; nf2 < 4; ++nf2) {
                    mma16816(acc[mf][nf2 * 2],     a[mf], b[nf2][0], b[nf2][1]);
                    mma16816(acc[mf][nf2 * 2 + 1], a[mf], b[nf2][2], b[nf2][3]);
                }
            }
        }
    }

    // ---- Epilogue: fused scale/bias, float2 stores ----
    const int ncol0 = n0 + wnb;
    float2 sc[8], bi[8];
    #pragma unroll
    for (int nf = 0; nf < 8; ++nf) {
        int c = nf * 8 + (lid & 3) * 2;
        sc[nf] = *reinterpret_cast<const float2*>(scale + ncol0 + c);
        bi[nf] = *reinterpret_cast<const float2*>(bias + ncol0 + c);
    }
    #pragma unroll
    for (int mf = 0; mf < 4; ++mf) {
        int r0 = m0 + wmb + mf * 16 + (lid >> 2);
        float* out0 = out + (size_t)r0 * N_DIM + ncol0;
        float* out1 = out0 + (size_t)8 * N_DIM;
        #pragma unroll
        for (int nf = 0; nf < 8; ++nf) {
            int c = nf * 8 + (lid & 3) * 2;
            float2 v0 = make_float2(fmaf(acc[mf][nf][0], sc[nf].x, bi[nf].x),
                                    fmaf(acc[mf][nf][1], sc[nf].y, bi[nf].y));
            float2 v1 = make_float2(fmaf(acc[mf][nf][2], sc[nf].x, bi[nf].x),
                                    fmaf(acc[mf][nf][3], sc[nf].y, bi[nf].y));
            *reinterpret_cast<float2*>(out0 + c) = v0;
            *reinterpret_cast<float2*>(out1 + c) = v1;
        }
    }
}

// ---------------------------------------------------------------------------
// Host launch — inputs identified by element count.
// ---------------------------------------------------------------------------
extern "C" void kernel_launch(void* const* d_in, const int* in_sizes, int n_in,
                              void* d_out, int out_size) {
    int xi = 0, wi = 1, sm1 = -1, sm2 = -1;
    for (int i = 0; i < 4; ++i) {
        if (in_sizes[i] == M_ROWS * K_DIM)      xi = i;
        else if (in_sizes[i] == K_DIM * N_DIM)  wi = i;
        else if (sm1 < 0)                       sm1 = i;
        else                                    sm2 = i;
    }
    int si, bi2;
    if (xi < sm1) { si = sm1; bi2 = sm2; }   // dict order: x, w, scale, bias
    else          { bi2 = sm1; si = sm2; }   // alphabetical fallback

    const float* x     = (const float*)d_in[xi];
    const int*   w     = (const int*)d_in[wi];     // int8 delivered as int32
    const float* scale = (const float*)d_in[si];
    const float* bias  = (const float*)d_in[bi2];
    float*       out   = (float*)d_out;

    void* xh = nullptr; cudaGetSymbolAddress(&xh, g_xh);
    void* wh = nullptr; cudaGetSymbolAddress(&wh, g_wh);

    int nx4 = M_ROWS * K_DIM / 4;
    cvt_x_kernel<<<nx4 / 256, 256>>>((const float4*)x, (__half2*)xh, nx4);
    cvt_w_kernel<<<dim3(N_DIM / 32, K_DIM / 32), dim3(32, 8)>>>(w, (__half*)wh);

    cudaFuncSetAttribute(qgemm_kernel, cudaFuncAttributeMaxDynamicSharedMemorySize,
                         SMEM_BYTES);
    int grid = (M_ROWS / BM) * (N_DIM / BN);   // 4096
    qgemm_kernel<<<grid, 256, SMEM_BYTES>>>(scale, bias, out);
}

// round 8
// speedup vs baseline: 1.2226x; 1.0532x over previous
#include <cuda_runtime.h>
#include <cuda_fp16.h>
#include <cstdint>

// ---------------------------------------------------------------------------
// y[8192,16384] = x[8192,4096] @ dequant(W[4096,16384]) * scale + bias
// Weight arrives as int32 (harness dtype set is f32/i32/bf16).
// R8: 128x128 CTA tile, 128 threads (4 warps @ 64x64), 3-stage BK=64 pipeline,
//     2 CTAs/SM so barrier skew of one CTA is filled by the other.
// ---------------------------------------------------------------------------
static constexpr int M_ROWS = 8192;
static constexpr int K_DIM  = 4096;
static constexpr int N_DIM  = 16384;

static constexpr int BM = 128;
static constexpr int BN = 128;
static constexpr int BK = 64;
static constexpr int STAGES = 3;
static constexpr int NITER  = K_DIM / BK;     // 64

static constexpr int A_LD = BK + 8;           // 72 halves = 144 B (16B mult)
static constexpr int B_LD = BK + 8;
static constexpr int A_ST = BM * A_LD;        // 9216 halves
static constexpr int B_ST = BN * B_LD;        // 9216 halves
static constexpr int STG  = A_ST + B_ST;      // 18432 halves = 36864 B
static constexpr int SMEM_BYTES = STAGES * STG * 2;   // 110592 B -> 2 CTAs/SM

__device__ __half g_xh[(size_t)M_ROWS * K_DIM];   //  64 MiB  [M][K]
__device__ __half g_wh[(size_t)N_DIM * K_DIM];    // 128 MiB  [N][K]

// ---------------------------------------------------------------------------
__device__ __forceinline__ uint32_t smem_u32(const void* p) {
    uint32_t a;
    asm("{ .reg .u64 t; cvta.to.shared.u64 t, %1; cvt.u32.u64 %0, t; }" : "=r"(a) : "l"(p));
    return a;
}

__device__ __forceinline__ void cp16(uint32_t dst, const void* src) {
    asm volatile("cp.async.cg.shared.global [%0], [%1], 16;" :: "r"(dst), "l"(src));
}

#define CP_COMMIT() asm volatile("cp.async.commit_group;" ::: "memory")

__device__ __forceinline__ void ldsm4(uint32_t* r, uint32_t addr) {
    asm volatile("ldmatrix.sync.aligned.m8n8.x4.shared.b16 {%0,%1,%2,%3}, [%4];"
                 : "=r"(r[0]), "=r"(r[1]), "=r"(r[2]), "=r"(r[3]) : "r"(addr));
}

__device__ __forceinline__ void mma16816(float* d, const uint32_t* a, uint32_t b0, uint32_t b1) {
    asm volatile(
        "mma.sync.aligned.m16n8k16.row.col.f32.f16.f16.f32 "
        "{%0,%1,%2,%3}, {%4,%5,%6,%7}, {%8,%9}, {%0,%1,%2,%3};"
        : "+f"(d[0]), "+f"(d[1]), "+f"(d[2]), "+f"(d[3])
        : "r"(a[0]), "r"(a[1]), "r"(a[2]), "r"(a[3]), "r"(b0), "r"(b1));
}

// ---------------------------------------------------------------------------
// Prep kernels
// ---------------------------------------------------------------------------
__global__ void cvt_x_kernel(const float4* __restrict__ x, __half2* __restrict__ out, int n4) {
    int i = blockIdx.x * blockDim.x + threadIdx.x;
    if (i < n4) {
        float4 v = x[i];
        out[2 * i]     = __floats2half2_rn(v.x, v.y);
        out[2 * i + 1] = __floats2half2_rn(v.z, v.w);
    }
}

// W[k][n] int32 row-major -> Wh[n][k] fp16 (exact), 32x32 smem transpose
__global__ void cvt_w_kernel(const int* __restrict__ w, __half* __restrict__ out) {
    __shared__ int t[32][33];
    int n0 = blockIdx.x * 32, k0 = blockIdx.y * 32;
    int tx = threadIdx.x, ty = threadIdx.y;
    #pragma unroll
    for (int i = ty; i < 32; i += 8)
        t[i][tx] = w[(size_t)(k0 + i) * N_DIM + n0 + tx];
    __syncthreads();
    #pragma unroll
    for (int i = ty; i < 32; i += 8)
        out[(size_t)(n0 + i) * K_DIM + k0 + tx] = __int2half_rn(t[tx][i]);
}

// ---------------------------------------------------------------------------
// Main GEMM
// ---------------------------------------------------------------------------
__global__ void __launch_bounds__(128, 2) qgemm_kernel(
    const float* __restrict__ scale,
    const float* __restrict__ bias,
    float* __restrict__ out)
{
    extern __shared__ __align__(16) char smem_raw[];
    const uint32_t sb = smem_u32(smem_raw);
    const int tid = threadIdx.x;
    const int wid = tid >> 5;
    const int lid = tid & 31;

    // Raster: groups of 8 N-tiles x all 64 M-tiles (512 CTAs/group)
    const int bid = blockIdx.x;
    const int group  = bid >> 9;
    const int within = bid & 511;
    const int nt = (group << 3) | (within & 7);
    const int mt = within >> 3;
    const int m0 = mt * BM;
    const int n0 = nt * BN;

    const __half* __restrict__ xh = g_xh;
    const __half* __restrict__ wh = g_wh;

    auto issue_stage = [&](int it) {
        const int k0 = it * BK;
        const uint32_t base = sb + (uint32_t)(it % STAGES) * (STG * 2);
        // A: 128 rows x 8 chunks = 1024 -> 8/thread (row-pair per thread)
        #pragma unroll
        for (int j = 0; j < 8; ++j) {
            int ci = tid + 128 * j;
            int row = ci >> 3, cc = ci & 7;
            cp16(base + (uint32_t)(row * A_LD + cc * 8) * 2,
                 xh + (size_t)(m0 + row) * K_DIM + k0 + cc * 8);
        }
        // B: 128 rows x 8 chunks = 1024 -> 8/thread
        #pragma unroll
        for (int j = 0; j < 8; ++j) {
            int ci = tid + 128 * j;
            int row = ci >> 3, cc = ci & 7;
            cp16(base + (uint32_t)(A_ST + row * B_LD + cc * 8) * 2,
                 wh + (size_t)(n0 + row) * K_DIM + k0 + cc * 8);
        }
        CP_COMMIT();
    };

    // 4 warps: wid&1 -> M half (64), wid>>1 -> N half (64)
    const int wmb = (wid & 1) * 64;
    const int wnb = (wid >> 1) * 64;

    float acc[4][8][4];
    #pragma unroll
    for (int i = 0; i < 4; ++i)
        #pragma unroll
        for (int j = 0; j < 8; ++j)
            #pragma unroll
            for (int k = 0; k < 4; ++k) acc[i][j][k] = 0.0f;

    issue_stage(0);
    issue_stage(1);

    const int a_row_lane = lid & 15;
    const int a_col_lane = (lid >> 4) * 8;
    const int b_row_lane = (lid & 7) | ((lid >> 4) << 3);
    const int b_col_lane = ((lid >> 3) & 1) * 8;

    #pragma unroll 1
    for (int it = 0; it < NITER; ++it) {
        asm volatile("cp.async.wait_group 1;" ::: "memory");
        __syncthreads();
        if (it + 2 < NITER) issue_stage(it + 2);
        else CP_COMMIT();   // keep 1 commit/iter so wait_group count stays valid

        const uint32_t base = sb + (uint32_t)(it % STAGES) * (STG * 2);
        #pragma unroll
        for (int ks = 0; ks < BK / 16; ++ks) {
            uint32_t a[4][4], b[4][4];
            #pragma unroll
            for (int mf = 0; mf < 4; ++mf) {
                int row = wmb + mf * 16 + a_row_lane;
                int col = ks * 16 + a_col_lane;
                ldsm4(a[mf], base + (uint32_t)(row * A_LD + col) * 2);
            }
            #pragma unroll
            for (int nf2 = 0; nf2 < 4; ++nf2) {
                int row = wnb + nf2 * 16 + b_row_lane;
                int col = ks * 16 + b_col_lane;
                ldsm4(b[nf2], base + (uint32_t)(A_ST + row * B_LD + col) * 2);
            }
            #pragma unroll
            for (int mf = 0; mf < 4; ++mf) {
                #pragma unroll
                for (int nf2 = 0; nf2 < 4; ++nf2) {
                    mma16816(acc[mf][nf2 * 2],     a[mf], b[nf2][0], b[nf2][1]);
                    mma16816(acc[mf][nf2 * 2 + 1], a[mf], b[nf2][2], b[nf2][3]);
                }
            }
        }
    }

    // ---- Epilogue: fused scale/bias, float2 stores ----
    const int ncol0 = n0 + wnb;
    float2 sc[8], bi[8];
    #pragma unroll
    for (int nf = 0; nf < 8; ++nf) {
        int c = nf * 8 + (lid & 3) * 2;
        sc[nf] = *reinterpret_cast<const float2*>(scale + ncol0 + c);
        bi[nf] = *reinterpret_cast<const float2*>(bias + ncol0 + c);
    }
    #pragma unroll
    for (int mf = 0; mf < 4; ++mf) {
        int r0 = m0 + wmb + mf * 16 + (lid >> 2);
        float* out0 = out + (size_t)r0 * N_DIM + ncol0;
        float* out1 = out0 + (size_t)8 * N_DIM;
        #pragma unroll
        for (int nf = 0; nf < 8; ++nf) {
            int c = nf * 8 + (lid & 3) * 2;
            float2 v0 = make_float2(fmaf(acc[mf][nf][0], sc[nf].x, bi[nf].x),
                                    fmaf(acc[mf][nf][1], sc[nf].y, bi[nf].y));
            float2 v1 = make_float2(fmaf(acc[mf][nf][2], sc[nf].x, bi[nf].x),
                                    fmaf(acc[mf][nf][3], sc[nf].y, bi[nf].y));
            *reinterpret_cast<float2*>(out0 + c) = v0;
            *reinterpret_cast<float2*>(out1 + c) = v1;
        }
    }
}

// ---------------------------------------------------------------------------
// Host launch — inputs identified by element count.
// ---------------------------------------------------------------------------
extern "C" void kernel_launch(void* const* d_in, const int* in_sizes, int n_in,
                              void* d_out, int out_size) {
    int xi = 0, wi = 1, sm1 = -1, sm2 = -1;
    for (int i = 0; i < 4; ++i) {
        if (in_sizes[i] == M_ROWS * K_DIM)      xi = i;
        else if (in_sizes[i] == K_DIM * N_DIM)  wi = i;
        else if (sm1 < 0)                       sm1 = i;
        else                                    sm2 = i;
    }
    int si, bi2;
    if (xi < sm1) { si = sm1; bi2 = sm2; }   // dict order: x, w, scale, bias
    else          { bi2 = sm1; si = sm2; }   // alphabetical fallback

    const float* x     = (const float*)d_in[xi];
    const int*   w     = (const int*)d_in[wi];     // int8 delivered as int32
    const float* scale = (const float*)d_in[si];
    const float* bias  = (const float*)d_in[bi2];
    float*       out   = (float*)d_out;

    void* xh = nullptr; cudaGetSymbolAddress(&xh, g_xh);
    void* wh = nullptr; cudaGetSymbolAddress(&wh, g_wh);

    int nx4 = M_ROWS * K_DIM / 4;
    cvt_x_kernel<<<nx4 / 256, 256>>>((const float4*)x, (__half2*)xh, nx4);
    cvt_w_kernel<<<dim3(N_DIM / 32, K_DIM / 32), dim3(32, 8)>>>(w, (__half*)wh);

    cudaFuncSetAttribute(qgemm_kernel, cudaFuncAttributeMaxDynamicSharedMemorySize,
                         SMEM_BYTES);
    int grid = (M_ROWS / BM) * (N_DIM / BN);   // 8192
    qgemm_kernel<<<grid, 128, SMEM_BYTES>>>(scale, bias, out);
}